// round 11
// baseline (speedup 1.0000x reference)
#include <cuda_runtime.h>
#include <cuda_fp16.h>
#include <cstdint>
#include <math.h>

// ---------------- problem dims ----------------
#define SEQ   512
#define BATCH 64
#define INPUT 256
#define HID   1024

// ---------------- config ----------------
#define NCTA  256            // 64 m-groups x 4 k-slices, 2 CTAs/SM
#define NTHR  128
#define NM    64             // m-groups (64 gate-rows each: 4 gates x 16 j)
#define NKS   4              // k slices (320 k each: 256 h + 64 x)
#define RPC   64             // gate-rows per CTA
#define ASTR  656            // smem row stride bytes (320*2 + 16 pad)
#define OFF_A 0
#define OFF_B (RPC*ASTR)                    // 41984
#define SMEM_TOTAL (RPC*ASTR + BATCH*ASTR)  // 83968

// ---------------- scratch ----------------
__device__ __align__(16) __half g_hh[2 * BATCH * HID];             // h fp16, double buffer
__device__ __align__(16) __half g_xh[(size_t)SEQ * BATCH * INPUT]; // x fp16
__device__ float    g_part[NKS * NM * RPC * BATCH];   // [ks][mg][row][b]  (4 MB)
// per-group counter lines, 256B per group: +0 = bar1 (partials), +32 = ready (pointwise)
__device__ unsigned g_grp[NM * 64];

struct Params {
    const float* x;
    const float* Wx[4]; const float* bx[4];
    const float* Wh[4]; const float* bh[4];
    float* out;
};

// ---------------- helpers ----------------
__device__ __forceinline__ uint32_t smem_u32(const void* p) {
    uint32_t a;
    asm("{ .reg .u64 t; cvta.to.shared.u64 t, %1; cvt.u32.u64 %0, t; }" : "=r"(a) : "l"(p));
    return a;
}
__device__ __forceinline__ void ldsm4(uint32_t* r, uint32_t addr) {
    asm volatile("ldmatrix.sync.aligned.m8n8.x4.shared.b16 {%0,%1,%2,%3}, [%4];"
        : "=r"(r[0]), "=r"(r[1]), "=r"(r[2]), "=r"(r[3]) : "r"(addr));
}
__device__ __forceinline__ void mma_f16(float* d, const uint32_t* a, const uint32_t* b) {
    asm volatile(
        "mma.sync.aligned.m16n8k16.row.col.f32.f16.f16.f32 "
        "{%0,%1,%2,%3}, {%4,%5,%6,%7}, {%8,%9}, {%0,%1,%2,%3};"
        : "+f"(d[0]), "+f"(d[1]), "+f"(d[2]), "+f"(d[3])
        : "r"(a[0]), "r"(a[1]), "r"(a[2]), "r"(a[3]), "r"(b[0]), "r"(b[1]));
}
__device__ __forceinline__ uint32_t pack2h(float va, float vb) {
    __half2 p = __halves2half2(__float2half_rn(va), __float2half_rn(vb));
    return *(uint32_t*)&p;
}
__device__ __forceinline__ float sigm(float x) { return 1.0f / (1.0f + __expf(-x)); }

// bar1: group-local (4 k-slice CTAs of one m-group)
__device__ __forceinline__ void group_barrier(volatile unsigned* c, unsigned target) {
    __syncthreads();
    if (threadIdx.x == 0) {
        __threadfence();
        atomicAdd((unsigned*)c, 1u);
        while (*c < target) __nanosleep(8);
        __threadfence();
    }
    __syncthreads();
}

// ---------------------------------------------------------------------------
// init: x -> fp16, zero h buffers, reset counters
__global__ void init_kernel(const float* __restrict__ x) {
    size_t i = (size_t)blockIdx.x * blockDim.x + threadIdx.x;
    if (i < (size_t)SEQ * BATCH * INPUT / 4) {
        float4 v = ((const float4*)x)[i];
        ((uint2*)g_xh)[i] = make_uint2(pack2h(v.x, v.y), pack2h(v.z, v.w));
    }
    if (i < (size_t)2 * BATCH * HID / 4) {
        ((uint2*)g_hh)[i] = make_uint2(0u, 0u);
    }
    if (i < NM * 64) g_grp[i] = 0u;
}

// ---------------------------------------------------------------------------
__global__ __launch_bounds__(NTHR, 2)
void lstm_mma(Params P) {
    extern __shared__ char smem[];
    const uint32_t sb = smem_u32(smem);

    const int tid  = threadIdx.x;
    const int w    = tid >> 5;
    const int l    = tid & 31;
    const int mg   = blockIdx.x >> 2;   // 0..63
    const int ks   = blockIdx.x & 3;    // 0..3
    const int j0   = mg * 16;
    volatile unsigned* grpc   = &g_grp[mg * 64];
    unsigned*          readyc = (unsigned*)&g_grp[mg * 64 + 32];

    // dep-poll line for threads 1..17: 16 dep groups (h source) + self (partials WAR)
    volatile unsigned* depc = 0;
    if (tid >= 1 && tid <= 17) {
        int pt = tid - 1;
        int dg = (pt < 16) ? (ks * 16 + pt) : mg;
        depc = &g_grp[dg * 64 + 32];
    }

    // ---- stage weights into smem (single fp16), once per launch ----
    // 64 rows x 320 k; 2 threads per row, 160 k each
    {
        const int r    = tid >> 1;           // 0..63
        const int half = tid & 1;
        const int gate = r >> 4, jl = r & 15, j = j0 + jl;
        const float* whp = P.Wh[gate] + (size_t)j * HID + ks * 256;
        const float* wxp = P.Wx[gate] + (size_t)j * INPUT + ks * 64;
        char* arow = smem + OFF_A + r * ASTR;
        #pragma unroll 4
        for (int fi = 0; fi < 40; fi++) {
            int k = (half * 40 + fi) * 4;     // 0..316
            float4 v = (k < 256) ? *(const float4*)(whp + k)
                                 : *(const float4*)(wxp + (k - 256));
            *(uint2*)(arow + k * 2) = make_uint2(pack2h(v.x, v.y), pack2h(v.z, v.w));
        }
    }

    // ---- warp tile: 32 rows x 32 cols; 4 warps in 2x2 grid ----
    const int wm = w & 1;
    const int wn = w >> 1;
    const uint32_t a_row  = (uint32_t)(wm * 32 + (l & 15));
    const uint32_t a_colb = (uint32_t)((l >> 4) * 16);
    const uint32_t aAddr0 = sb + OFF_A + a_row * ASTR + a_colb;
    const uint32_t aAddr1 = aAddr0 + 16 * ASTR;
    // B ldsm4: lanes 0-15 -> n-tile pair low (rows +0..7), lanes 16-31 -> +8 rows
    const uint32_t bAddr  = sb + OFF_B
        + (uint32_t)(wn * 32 + (l & 7) + ((l >> 4) & 1) * 8) * ASTR
        + (uint32_t)(((l >> 3) & 1) * 16);

    // ---- pointwise cell ownership: 2 cells per thread ----
    const int pb  = ks * 16 + (tid & 15);    // batch
    const int jlA = tid >> 4;                // 0..7
    const int jlB = jlA + 8;
    const int jA  = j0 + jlA, jB = j0 + jlB;
    float biasA[4], biasB[4];
    #pragma unroll
    for (int g = 0; g < 4; g++) {
        biasA[g] = P.bh[g][jA] + P.bx[g][jA];
        biasB[g] = P.bh[g][jB] + P.bx[g][jB];
    }
    float cA = 0.0f, cB = 0.0f;

    float* out = P.out;
    const size_t BH  = (size_t)BATCH * HID;
    const size_t SBH = (size_t)SEQ * BH;

    // staging map: thread -> (batch stb = tid>>1, segment stf = tid&1)
    const int stb = tid >> 1;           // 0..63
    const int stf = tid & 1;            // 0..1
    const size_t hoff = (size_t)stb * HID + ks * 256 + stf * 128;  // 128 fp16 = 256B
    char* b_row = smem + OFF_B + stb * ASTR;
    const size_t x_off = (size_t)stb * INPUT + ks * 64 + stf * 32; // 32 fp16 = 64B

    float* ppart = g_part + (size_t)(ks * NM + mg) * RPC * BATCH;

    // ---- pre-loop: stage x(0) and h(0) (buffer 0 = zeros) ----
    {
        const uint4* xs = (const uint4*)(g_xh + x_off);
        #pragma unroll
        for (int q = 0; q < 4; q++)
            *(uint4*)(b_row + 512 + stf * 64 + q * 16) = __ldcg(xs + q);
        const uint4* hs = (const uint4*)(g_hh + hoff);
        #pragma unroll
        for (int q = 0; q < 16; q++)
            *(uint4*)(b_row + stf * 256 + q * 16) = __ldcg(hs + q);
    }
    __syncthreads();

    for (int t = 0; t < SEQ; t++) {
        // ---- GEMM: D[64 rows][64 b] = A * B, single-pass fp16 ----
        float d[2][4][4];
        #pragma unroll
        for (int mt = 0; mt < 2; mt++)
            #pragma unroll
            for (int nt = 0; nt < 4; nt++)
                #pragma unroll
                for (int q = 0; q < 4; q++) d[mt][nt][q] = 0.0f;

        for (int kt = 0; kt < 20; kt++) {
            const uint32_t kb = (uint32_t)(kt * 32);
            uint32_t A0[4], A1[4];
            ldsm4(A0, aAddr0 + kb);
            ldsm4(A1, aAddr1 + kb);
            #pragma unroll
            for (int np = 0; np < 2; np++) {            // n-tile pairs
                uint32_t B4[4];
                ldsm4(B4, bAddr + (uint32_t)(np * 16 * ASTR) + kb);
                mma_f16(d[0][np * 2 + 0], A0, B4 + 0);
                mma_f16(d[1][np * 2 + 0], A1, B4 + 0);
                mma_f16(d[0][np * 2 + 1], A0, B4 + 2);
                mma_f16(d[1][np * 2 + 1], A1, B4 + 2);
            }
        }

        // ---- store partials [row][b] ----
        {
            const int r0 = wm * 32 + (l >> 2);
            const int c0 = wn * 32 + (l & 3) * 2;
            #pragma unroll
            for (int mt = 0; mt < 2; mt++) {
                #pragma unroll
                for (int nt = 0; nt < 4; nt++) {
                    int row = r0 + mt * 16;
                    int col = c0 + nt * 8;
                    *(float2*)(ppart + (size_t)row * BATCH + col) =
                        make_float2(d[mt][nt][0], d[mt][nt][1]);
                    *(float2*)(ppart + (size_t)(row + 8) * BATCH + col) =
                        make_float2(d[mt][nt][2], d[mt][nt][3]);
                }
            }
        }

        // ---- B smem reads done -> stage x(t+1) (overlaps bar1) ----
        __syncthreads();
        if (t + 1 < SEQ) {
            const uint4* xs = (const uint4*)(g_xh + (size_t)(t + 1) * BATCH * INPUT + x_off);
            #pragma unroll
            for (int q = 0; q < 4; q++)
                *(uint4*)(b_row + 512 + stf * 64 + q * 16) = __ldcg(xs + q);
        }

        // ---- bar1: group-local (4 CTAs) ----
        group_barrier(grpc, (unsigned)(t + 1) * NKS);

        // ---- reduce 4 k-slices + pointwise (2 cells); h -> buf[(t+1)&1] ----
        {
            const size_t hw = (size_t)((t + 1) & 1) * BH;
            float accA[4], accB[4];
            #pragma unroll
            for (int g = 0; g < 4; g++) { accA[g] = biasA[g]; accB[g] = biasB[g]; }
            #pragma unroll
            for (int g = 0; g < 4; g++) {
                #pragma unroll
                for (int s = 0; s < NKS; s++) {
                    const float* pp = g_part + (size_t)(s * NM + mg) * RPC * BATCH + pb;
                    accA[g] += __ldcg(pp + (size_t)(g * 16 + jlA) * BATCH);
                    accB[g] += __ldcg(pp + (size_t)(g * 16 + jlB) * BATCH);
                }
            }
            float f, i1, i2, o, hv;

            f = sigm(accA[0]); i1 = sigm(accA[1]); i2 = tanhf(accA[2]); o = sigm(accA[3]);
            cA = cA * f + i1 * i2;
            hv = tanhf(cA) * o;
            out[(size_t)t * BH + (size_t)pb * HID + jA] = hv;
            g_hh[hw + (size_t)pb * HID + jA] = __float2half_rn(hv);
            if (t == SEQ - 1) {
                out[SBH + (size_t)pb * HID + jA] = hv;
                out[SBH + BH + (size_t)pb * HID + jA] = cA;
            }

            f = sigm(accB[0]); i1 = sigm(accB[1]); i2 = tanhf(accB[2]); o = sigm(accB[3]);
            cB = cB * f + i1 * i2;
            hv = tanhf(cB) * o;
            out[(size_t)t * BH + (size_t)pb * HID + jB] = hv;
            g_hh[hw + (size_t)pb * HID + jB] = __float2half_rn(hv);
            if (t == SEQ - 1) {
                out[SBH + (size_t)pb * HID + jB] = hv;
                out[SBH + BH + (size_t)pb * HID + jB] = cB;
            }
        }

        if (t + 1 < SEQ) {
            // ---- ready signal: this group's pointwise(t) done ----
            __syncthreads();
            if (tid == 0) {
                __threadfence();
                atomicAdd(readyc, 1u);
            }
            // ---- dep-wait: 16 dep groups + self ready >= (t+1)*4 ----
            if (tid >= 1 && tid <= 17) {
                const unsigned tgt = (unsigned)(t + 1) * NKS;
                while (*depc < tgt) __nanosleep(16);
                __threadfence();
            }
            __syncthreads();

            // ---- stage h(t+1) from buf[(t+1)&1] ----
            const uint4* hs = (const uint4*)(g_hh + (size_t)((t + 1) & 1) * BH + hoff);
            #pragma unroll
            for (int q = 0; q < 16; q++)
                *(uint4*)(b_row + stf * 256 + q * 16) = __ldcg(hs + q);
            __syncthreads();
        }
    }
}

// ---------------------------------------------------------------------------
extern "C" void kernel_launch(void* const* d_in, const int* in_sizes, int n_in,
                              void* d_out, int out_size) {
    Params P;
    P.x = (const float*)d_in[0];
    P.Wx[0] = (const float*)d_in[1];  P.bx[0] = (const float*)d_in[2];
    P.Wx[1] = (const float*)d_in[3];  P.bx[1] = (const float*)d_in[4];
    P.Wx[2] = (const float*)d_in[5];  P.bx[2] = (const float*)d_in[6];
    P.Wx[3] = (const float*)d_in[7];  P.bx[3] = (const float*)d_in[8];
    P.Wh[0] = (const float*)d_in[9];  P.bh[0] = (const float*)d_in[10];
    P.Wh[1] = (const float*)d_in[11]; P.bh[1] = (const float*)d_in[12];
    P.Wh[2] = (const float*)d_in[13]; P.bh[2] = (const float*)d_in[14];
    P.Wh[3] = (const float*)d_in[15]; P.bh[3] = (const float*)d_in[16];
    P.out   = (float*)d_out;

    static bool attr_set = false;
    if (!attr_set) {
        cudaFuncSetAttribute(lstm_mma, cudaFuncAttributeMaxDynamicSharedMemorySize,
                             SMEM_TOTAL);
        attr_set = true;
    }

    init_kernel<<<(SEQ * BATCH * INPUT / 4 + 255) / 256, 256>>>(P.x);
    lstm_mma<<<NCTA, NTHR, SMEM_TOTAL>>>(P);
}

// round 12
// speedup vs baseline: 1.1546x; 1.1546x over previous
#include <cuda_runtime.h>
#include <cuda_fp16.h>
#include <cstdint>
#include <math.h>

// ---------------- problem dims ----------------
#define SEQ   512
#define BATCH 64
#define INPUT 256
#define HID   1024

// ---------------- config ----------------
#define NCTA  128            // 32 m-groups x 4 k-slices
#define NTHR  256
#define NM    32             // m-groups (128 gate-rows each: 4 gates x 32 j)
#define NKS   4              // k slices (320 k each: 256 h + 64 x)
#define RPC   128            // gate-rows per CTA
#define ASTR  656            // smem row stride bytes (320*2 + 16 pad)
#define OFF_A 0
#define OFF_B (RPC*ASTR)                    // 83968
#define OFF_H (OFF_B + BATCH*ASTR)          // h exchange area, 1KB
#define OFF_O (OFF_H + 1024)                // out exchange area, 2KB
#define SMEM_TOTAL (OFF_O + 2048)           // 129024

// ---------------- scratch ----------------
__device__ __align__(16) __half g_hh[2 * BATCH * HID];             // h fp16, double buffer
__device__ __align__(16) __half g_xh[(size_t)SEQ * BATCH * INPUT]; // x fp16
__device__ float    g_part[NKS * NM * RPC * BATCH];   // [ks][mg][row][b]  (4 MB)
// per-group counter lines, 256B per group: +0 = bar1 (partials), +32 = ready (pointwise)
__device__ unsigned g_grp[NM * 64];

struct Params {
    const float* x;
    const float* Wx[4]; const float* bx[4];
    const float* Wh[4]; const float* bh[4];
    float* out;
};

// ---------------- helpers ----------------
__device__ __forceinline__ uint32_t smem_u32(const void* p) {
    uint32_t a;
    asm("{ .reg .u64 t; cvta.to.shared.u64 t, %1; cvt.u32.u64 %0, t; }" : "=r"(a) : "l"(p));
    return a;
}
__device__ __forceinline__ void ldsm4(uint32_t* r, uint32_t addr) {
    asm volatile("ldmatrix.sync.aligned.m8n8.x4.shared.b16 {%0,%1,%2,%3}, [%4];"
        : "=r"(r[0]), "=r"(r[1]), "=r"(r[2]), "=r"(r[3]) : "r"(addr));
}
__device__ __forceinline__ void mma_f16(float* d, const uint32_t* a, const uint32_t* b) {
    asm volatile(
        "mma.sync.aligned.m16n8k16.row.col.f32.f16.f16.f32 "
        "{%0,%1,%2,%3}, {%4,%5,%6,%7}, {%8,%9}, {%0,%1,%2,%3};"
        : "+f"(d[0]), "+f"(d[1]), "+f"(d[2]), "+f"(d[3])
        : "r"(a[0]), "r"(a[1]), "r"(a[2]), "r"(a[3]), "r"(b[0]), "r"(b[1]));
}
__device__ __forceinline__ uint32_t pack2h(float va, float vb) {
    __half2 p = __halves2half2(__float2half_rn(va), __float2half_rn(vb));
    return *(uint32_t*)&p;
}
__device__ __forceinline__ float sigm(float x) { return 1.0f / (1.0f + __expf(-x)); }

// bar1: group-local (4 k-slice CTAs of one m-group)
__device__ __forceinline__ void group_barrier(volatile unsigned* c, unsigned target) {
    __syncthreads();
    if (threadIdx.x == 0) {
        __threadfence();
        atomicAdd((unsigned*)c, 1u);
        while (*c < target) __nanosleep(8);
        __threadfence();
    }
    __syncthreads();
}

// ---------------------------------------------------------------------------
// init: x -> fp16, zero h buffers, reset counters
__global__ void init_kernel(const float* __restrict__ x) {
    size_t i = (size_t)blockIdx.x * blockDim.x + threadIdx.x;
    if (i < (size_t)SEQ * BATCH * INPUT / 4) {
        float4 v = ((const float4*)x)[i];
        ((uint2*)g_xh)[i] = make_uint2(pack2h(v.x, v.y), pack2h(v.z, v.w));
    }
    if (i < (size_t)2 * BATCH * HID / 4) {
        ((uint2*)g_hh)[i] = make_uint2(0u, 0u);
    }
    if (i < NM * 64) g_grp[i] = 0u;
}

// ---------------------------------------------------------------------------
__global__ __launch_bounds__(NTHR, 1)
void lstm_mma(Params P) {
    extern __shared__ char smem[];
    const uint32_t sb = smem_u32(smem);

    const int tid  = threadIdx.x;
    const int w    = tid >> 5;
    const int l    = tid & 31;
    const int mg   = blockIdx.x >> 2;   // 0..31
    const int ks   = blockIdx.x & 3;    // 0..3
    const int j0   = mg * 32;
    volatile unsigned* grpc   = &g_grp[mg * 64];
    unsigned*          readyc = (unsigned*)&g_grp[mg * 64 + 32];

    // dep-poll line for threads 1..9: 8 dep groups (h source) + self (partials WAR)
    volatile unsigned* depc = 0;
    if (tid >= 1 && tid <= 9) {
        int pt = tid - 1;
        int dg = (pt < 8) ? (ks * 8 + pt) : mg;
        depc = &g_grp[dg * 64 + 32];
    }

    // ---- stage weights into smem (single fp16), once per launch ----
    {
        const int r    = tid >> 1;           // 0..127
        const int half = tid & 1;
        const int gate = r >> 5, jl = r & 31, j = j0 + jl;
        const float* whp = P.Wh[gate] + (size_t)j * HID + ks * 256;
        const float* wxp = P.Wx[gate] + (size_t)j * INPUT + ks * 64;
        char* arow = smem + OFF_A + r * ASTR;
        #pragma unroll 4
        for (int fi = 0; fi < 40; fi++) {
            int k = (half * 40 + fi) * 4;     // 0..316
            float4 v = (k < 256) ? *(const float4*)(whp + k)
                                 : *(const float4*)(wxp + (k - 256));
            *(uint2*)(arow + k * 2) = make_uint2(pack2h(v.x, v.y), pack2h(v.z, v.w));
        }
    }

    // ---- warp tile: 32 rows x 32 cols ----
    const int wm = w & 3;
    const int wn = w >> 2;
    const uint32_t a_row  = (uint32_t)(wm * 32 + (l & 15));
    const uint32_t a_colb = (uint32_t)((l >> 4) * 16);
    const uint32_t aAddr0 = sb + OFF_A + a_row * ASTR + a_colb;
    const uint32_t aAddr1 = aAddr0 + 16 * ASTR;
    // B ldsm4: covers 2 n-tiles (16 batch rows) per load
    const uint32_t bAddr  = sb + OFF_B
        + (uint32_t)(wn * 32 + (l & 7) + ((l >> 4) & 1) * 8) * ASTR
        + (uint32_t)(((l >> 3) & 1) * 16);

    // ---- pointwise cell ownership: 2 cells per thread ----
    const int lb  = tid & 15;                // local batch 0..15
    const int pb  = ks * 16 + lb;            // global batch
    const int jlA = tid >> 4;                // 0..15
    const int jlB = jlA + 16;
    const int jA  = j0 + jlA, jB = j0 + jlB;
    float biasA[4], biasB[4];
    #pragma unroll
    for (int g = 0; g < 4; g++) {
        biasA[g] = P.bh[g][jA] + P.bx[g][jA];
        biasB[g] = P.bh[g][jB] + P.bx[g][jB];
    }
    float cA = 0.0f, cB = 0.0f;

    float* out = P.out;
    const size_t BH  = (size_t)BATCH * HID;
    const size_t SBH = (size_t)SEQ * BH;

    __half* harea = (__half*)(smem + OFF_H);   // [16 b][32 j] fp16
    float*  oarea = (float*)(smem + OFF_O);    // [16 b][32 j] fp32

    // staging map
    const int stb = tid >> 2;           // 0..63
    const int stf = tid & 3;            // 0..3
    const size_t hoff = (size_t)stb * HID + ks * 256 + stf * 64;   // 64 fp16 = 128B
    char* b_row = smem + OFF_B + stb * ASTR;
    const size_t x_off = (size_t)stb * INPUT + ks * 64 + stf * 16;

    float* ppart = g_part + (size_t)(ks * NM + mg) * RPC * BATCH;

    // ---- pre-loop: stage x(0) and h(0) (buffer 0 = zeros) ----
    {
        const uint4* xs = (const uint4*)(g_xh + x_off);
        *(uint4*)(b_row + 512 + stf * 32)      = __ldcg(xs + 0);
        *(uint4*)(b_row + 512 + stf * 32 + 16) = __ldcg(xs + 1);
        const uint4* hs = (const uint4*)(g_hh + hoff);
        #pragma unroll
        for (int q = 0; q < 8; q++)
            *(uint4*)(b_row + stf * 128 + q * 16) = __ldcg(hs + q);
    }
    __syncthreads();

    for (int t = 0; t < SEQ; t++) {
        // ---- GEMM: D[128 rows][64 b] = A * B, single-pass fp16 ----
        float d[2][4][4];
        #pragma unroll
        for (int mt = 0; mt < 2; mt++)
            #pragma unroll
            for (int nt = 0; nt < 4; nt++)
                #pragma unroll
                for (int q = 0; q < 4; q++) d[mt][nt][q] = 0.0f;

        for (int kt = 0; kt < 20; kt++) {
            const uint32_t kb = (uint32_t)(kt * 32);
            uint32_t A0[4], A1[4];
            ldsm4(A0, aAddr0 + kb);
            ldsm4(A1, aAddr1 + kb);
            #pragma unroll
            for (int np = 0; np < 2; np++) {
                uint32_t B4[4];
                ldsm4(B4, bAddr + (uint32_t)(np * 16 * ASTR) + kb);
                mma_f16(d[0][np * 2 + 0], A0, B4 + 0);
                mma_f16(d[1][np * 2 + 0], A1, B4 + 0);
                mma_f16(d[0][np * 2 + 1], A0, B4 + 2);
                mma_f16(d[1][np * 2 + 1], A1, B4 + 2);
            }
        }

        // ---- store partials [row][b] ----
        {
            const int r0 = wm * 32 + (l >> 2);
            const int c0 = wn * 32 + (l & 3) * 2;
            #pragma unroll
            for (int mt = 0; mt < 2; mt++) {
                #pragma unroll
                for (int nt = 0; nt < 4; nt++) {
                    int row = r0 + mt * 16;
                    int col = c0 + nt * 8;
                    *(float2*)(ppart + (size_t)row * BATCH + col) =
                        make_float2(d[mt][nt][0], d[mt][nt][1]);
                    *(float2*)(ppart + (size_t)(row + 8) * BATCH + col) =
                        make_float2(d[mt][nt][2], d[mt][nt][3]);
                }
            }
        }

        // ---- B smem reads done -> stage x(t+1) (overlaps bar1) ----
        __syncthreads();
        if (t + 1 < SEQ) {
            const uint4* xs = (const uint4*)(g_xh + (size_t)(t + 1) * BATCH * INPUT + x_off);
            *(uint4*)(b_row + 512 + stf * 32)      = __ldcg(xs + 0);
            *(uint4*)(b_row + 512 + stf * 32 + 16) = __ldcg(xs + 1);
        }

        // ---- bar1: group-local (4 CTAs) ----
        group_barrier(grpc, (unsigned)(t + 1) * NKS);

        const size_t hw = (size_t)((t + 1) & 1) * BH;

        // ---- reduce 4 k-slices + pointwise (2 cells) -> smem exchange ----
        {
            float accA[4], accB[4];
            #pragma unroll
            for (int g = 0; g < 4; g++) { accA[g] = biasA[g]; accB[g] = biasB[g]; }
            #pragma unroll
            for (int g = 0; g < 4; g++) {
                #pragma unroll
                for (int s = 0; s < NKS; s++) {
                    const float* pp = g_part + (size_t)(s * NM + mg) * RPC * BATCH + pb;
                    accA[g] += __ldcg(pp + (size_t)(g * 32 + jlA) * BATCH);
                    accB[g] += __ldcg(pp + (size_t)(g * 32 + jlB) * BATCH);
                }
            }
            float f, i1, i2, o, hvA, hvB;

            f = sigm(accA[0]); i1 = sigm(accA[1]); i2 = tanhf(accA[2]); o = sigm(accA[3]);
            cA = cA * f + i1 * i2;
            hvA = tanhf(cA) * o;

            f = sigm(accB[0]); i1 = sigm(accB[1]); i2 = tanhf(accB[2]); o = sigm(accB[3]);
            cB = cB * f + i1 * i2;
            hvB = tanhf(cB) * o;

            harea[lb * 32 + jlA] = __float2half_rn(hvA);
            harea[lb * 32 + jlB] = __float2half_rn(hvB);
            oarea[lb * 32 + jlA] = hvA;
            oarea[lb * 32 + jlB] = hvB;

            if (t == SEQ - 1) {      // final h, c (once; scattered is fine)
                out[SBH + (size_t)pb * HID + jA] = hvA;
                out[SBH + BH + (size_t)pb * HID + jA] = cA;
                out[SBH + (size_t)pb * HID + jB] = hvB;
                out[SBH + BH + (size_t)pb * HID + jB] = cB;
            }
        }
        __syncthreads();

        // ---- coalesced copies: h -> g_hh (64 thr), out (128 thr) ----
        if (tid < 64) {
            int b = tid >> 2, q = tid & 3;
            *(uint4*)(g_hh + hw + (size_t)(ks * 16 + b) * HID + j0 + q * 8) =
                *(uint4*)(harea + b * 32 + q * 8);
        }
        if (tid >= 128) {
            int u = tid - 128;
            int b = u >> 3, q = u & 7;
            *(float4*)(out + (size_t)t * BH + (size_t)(ks * 16 + b) * HID + j0 + q * 4) =
                *(float4*)(oarea + b * 32 + q * 4);
        }
        __syncthreads();

        if (t + 1 < SEQ) {
            // ---- ready signal: this group's pointwise(t) done ----
            if (tid == 0) {
                __threadfence();
                atomicAdd(readyc, 1u);
            }
            // ---- dep-wait: 8 dep groups + self ready >= (t+1)*4 ----
            if (tid >= 1 && tid <= 9) {
                const unsigned tgt = (unsigned)(t + 1) * NKS;
                while (*depc < tgt) __nanosleep(16);
                __threadfence();
            }
            __syncthreads();

            // ---- stage h(t+1) from buf[(t+1)&1] ----
            const uint4* hs = (const uint4*)(g_hh + hw + hoff);
            #pragma unroll
            for (int q = 0; q < 8; q++)
                *(uint4*)(b_row + stf * 128 + q * 16) = __ldcg(hs + q);
            __syncthreads();
        }
    }
}

// ---------------------------------------------------------------------------
extern "C" void kernel_launch(void* const* d_in, const int* in_sizes, int n_in,
                              void* d_out, int out_size) {
    Params P;
    P.x = (const float*)d_in[0];
    P.Wx[0] = (const float*)d_in[1];  P.bx[0] = (const float*)d_in[2];
    P.Wx[1] = (const float*)d_in[3];  P.bx[1] = (const float*)d_in[4];
    P.Wx[2] = (const float*)d_in[5];  P.bx[2] = (const float*)d_in[6];
    P.Wx[3] = (const float*)d_in[7];  P.bx[3] = (const float*)d_in[8];
    P.Wh[0] = (const float*)d_in[9];  P.bh[0] = (const float*)d_in[10];
    P.Wh[1] = (const float*)d_in[11]; P.bh[1] = (const float*)d_in[12];
    P.Wh[2] = (const float*)d_in[13]; P.bh[2] = (const float*)d_in[14];
    P.Wh[3] = (const float*)d_in[15]; P.bh[3] = (const float*)d_in[16];
    P.out   = (float*)d_out;

    static bool attr_set = false;
    if (!attr_set) {
        cudaFuncSetAttribute(lstm_mma, cudaFuncAttributeMaxDynamicSharedMemorySize,
                             SMEM_TOTAL);
        attr_set = true;
    }

    init_kernel<<<(SEQ * BATCH * INPUT / 4 + 255) / 256, 256>>>(P.x);
    lstm_mma<<<NCTA, NTHR, SMEM_TOTAL>>>(P);
}

// round 13
// speedup vs baseline: 1.2120x; 1.0498x over previous
#include <cuda_runtime.h>
#include <cuda_fp16.h>
#include <cstdint>
#include <math.h>

// ---------------- problem dims ----------------
#define SEQ   512
#define BATCH 64
#define INPUT 256
#define HID   1024

// ---------------- config ----------------
#define NCTA  128            // 32 m-groups x 4 k-slices
#define NTHR  256
#define NM    32             // m-groups (128 gate-rows each: 4 gates x 32 j)
#define NKS   4              // k slices (320 k each: 256 h + 64 x)
#define RPC   128            // gate-rows per CTA
#define ASTR  656            // smem row stride bytes (320*2 + 16 pad)
#define OFF_A 0
#define OFF_B (RPC*ASTR)                    // 83968
#define OFF_H (OFF_B + BATCH*ASTR)          // h exchange area, 1KB
#define OFF_O (OFF_H + 1024)                // out exchange area, 2KB
#define SMEM_TOTAL (OFF_O + 2048)           // 129024

// ---------------- scratch ----------------
__device__ __align__(16) __half g_hh[2 * BATCH * HID];             // h fp16, double buffer
__device__ __align__(16) __half g_xh[(size_t)SEQ * BATCH * INPUT]; // x fp16
__device__ float    g_part[NKS * NM * RPC * BATCH];   // [ks][mg][row][b]  (4 MB)
// per-group counter lines, 256B per group: +0 = bar1 (partials), +32 = ready (pointwise)
__device__ unsigned g_grp[NM * 64];

struct Params {
    const float* x;
    const float* Wx[4]; const float* bx[4];
    const float* Wh[4]; const float* bh[4];
    float* out;
};

// ---------------- helpers ----------------
__device__ __forceinline__ uint32_t smem_u32(const void* p) {
    uint32_t a;
    asm("{ .reg .u64 t; cvta.to.shared.u64 t, %1; cvt.u32.u64 %0, t; }" : "=r"(a) : "l"(p));
    return a;
}
__device__ __forceinline__ void ldsm4(uint32_t* r, uint32_t addr) {
    asm volatile("ldmatrix.sync.aligned.m8n8.x4.shared.b16 {%0,%1,%2,%3}, [%4];"
        : "=r"(r[0]), "=r"(r[1]), "=r"(r[2]), "=r"(r[3]) : "r"(addr));
}
__device__ __forceinline__ void mma_f16(float* d, const uint32_t* a, const uint32_t* b) {
    asm volatile(
        "mma.sync.aligned.m16n8k16.row.col.f32.f16.f16.f32 "
        "{%0,%1,%2,%3}, {%4,%5,%6,%7}, {%8,%9}, {%0,%1,%2,%3};"
        : "+f"(d[0]), "+f"(d[1]), "+f"(d[2]), "+f"(d[3])
        : "r"(a[0]), "r"(a[1]), "r"(a[2]), "r"(a[3]), "r"(b[0]), "r"(b[1]));
}
__device__ __forceinline__ uint32_t pack2h(float va, float vb) {
    __half2 p = __halves2half2(__float2half_rn(va), __float2half_rn(vb));
    return *(uint32_t*)&p;
}
__device__ __forceinline__ float sigm(float x) { return 1.0f / (1.0f + __expf(-x)); }

// ---------------------------------------------------------------------------
// init: x -> fp16, zero h buffers, reset counters
__global__ void init_kernel(const float* __restrict__ x) {
    size_t i = (size_t)blockIdx.x * blockDim.x + threadIdx.x;
    if (i < (size_t)SEQ * BATCH * INPUT / 4) {
        float4 v = ((const float4*)x)[i];
        ((uint2*)g_xh)[i] = make_uint2(pack2h(v.x, v.y), pack2h(v.z, v.w));
    }
    if (i < (size_t)2 * BATCH * HID / 4) {
        ((uint2*)g_hh)[i] = make_uint2(0u, 0u);
    }
    if (i < NM * 64) g_grp[i] = 0u;
}

// ---------------------------------------------------------------------------
__global__ __launch_bounds__(NTHR, 1)
void lstm_mma(Params P) {
    extern __shared__ char smem[];
    const uint32_t sb = smem_u32(smem);

    const int tid  = threadIdx.x;
    const int w    = tid >> 5;
    const int l    = tid & 31;
    const int mg   = blockIdx.x >> 2;   // 0..31
    const int ks   = blockIdx.x & 3;    // 0..3
    const int j0   = mg * 32;
    volatile unsigned* grpc   = &g_grp[mg * 64];
    unsigned*          readyc = (unsigned*)&g_grp[mg * 64 + 32];

    // dep-poll line for threads 1..9: 8 dep groups (h source) + self (partials WAR)
    volatile unsigned* depc = 0;
    if (tid >= 1 && tid <= 9) {
        int pt = tid - 1;
        int dg = (pt < 8) ? (ks * 8 + pt) : mg;
        depc = &g_grp[dg * 64 + 32];
    }

    // ---- stage weights into smem (single fp16), once per launch ----
    {
        const int r    = tid >> 1;           // 0..127
        const int half = tid & 1;
        const int gate = r >> 5, jl = r & 31, j = j0 + jl;
        const float* whp = P.Wh[gate] + (size_t)j * HID + ks * 256;
        const float* wxp = P.Wx[gate] + (size_t)j * INPUT + ks * 64;
        char* arow = smem + OFF_A + r * ASTR;
        #pragma unroll 4
        for (int fi = 0; fi < 40; fi++) {
            int k = (half * 40 + fi) * 4;     // 0..316
            float4 v = (k < 256) ? *(const float4*)(whp + k)
                                 : *(const float4*)(wxp + (k - 256));
            *(uint2*)(arow + k * 2) = make_uint2(pack2h(v.x, v.y), pack2h(v.z, v.w));
        }
    }

    // ---- warp tile: 32 rows x 32 cols ----
    const int wm = w & 3;
    const int wn = w >> 2;
    const uint32_t a_row  = (uint32_t)(wm * 32 + (l & 15));
    const uint32_t a_colb = (uint32_t)((l >> 4) * 16);
    const uint32_t aAddr0 = sb + OFF_A + a_row * ASTR + a_colb;
    const uint32_t aAddr1 = aAddr0 + 16 * ASTR;
    // B ldsm4: covers 2 n-tiles (16 batch rows) per load
    const uint32_t bAddr  = sb + OFF_B
        + (uint32_t)(wn * 32 + (l & 7) + ((l >> 4) & 1) * 8) * ASTR
        + (uint32_t)(((l >> 3) & 1) * 16);

    // ---- pointwise cell ownership: 2 cells per thread ----
    const int lb  = tid & 15;                // local batch 0..15
    const int pb  = ks * 16 + lb;            // global batch
    const int jlA = tid >> 4;                // 0..15
    const int jlB = jlA + 16;
    const int jA  = j0 + jlA, jB = j0 + jlB;
    float biasA[4], biasB[4];
    #pragma unroll
    for (int g = 0; g < 4; g++) {
        biasA[g] = P.bh[g][jA] + P.bx[g][jA];
        biasB[g] = P.bh[g][jB] + P.bx[g][jB];
    }
    float cA = 0.0f, cB = 0.0f;

    float* out = P.out;
    const size_t BH  = (size_t)BATCH * HID;
    const size_t SBH = (size_t)SEQ * BH;

    __half* harea = (__half*)(smem + OFF_H);   // [16 b][32 j] fp16
    float*  oarea = (float*)(smem + OFF_O);    // [16 b][32 j] fp32

    // staging map
    const int stb = tid >> 2;           // 0..63
    const int stf = tid & 3;            // 0..3
    const size_t hoff = (size_t)stb * HID + ks * 256 + stf * 64;   // 64 fp16 = 128B
    char* b_row = smem + OFF_B + stb * ASTR;
    const size_t x_off = (size_t)stb * INPUT + ks * 64 + stf * 16;

    float* ppart = g_part + (size_t)(ks * NM + mg) * RPC * BATCH;

    // ---- pre-loop: stage x(0) and h(0) (buffer 0 = zeros) ----
    {
        const uint4* xs = (const uint4*)(g_xh + x_off);
        *(uint4*)(b_row + 512 + stf * 32)      = __ldcg(xs + 0);
        *(uint4*)(b_row + 512 + stf * 32 + 16) = __ldcg(xs + 1);
        const uint4* hs = (const uint4*)(g_hh + hoff);
        #pragma unroll
        for (int q = 0; q < 8; q++)
            *(uint4*)(b_row + stf * 128 + q * 16) = __ldcg(hs + q);
    }
    __syncthreads();

    for (int t = 0; t < SEQ; t++) {
        // ---- GEMM: D[128 rows][64 b] = A * B, single-pass fp16 ----
        float d[2][4][4];
        #pragma unroll
        for (int mt = 0; mt < 2; mt++)
            #pragma unroll
            for (int nt = 0; nt < 4; nt++)
                #pragma unroll
                for (int q = 0; q < 4; q++) d[mt][nt][q] = 0.0f;

        for (int kt = 0; kt < 20; kt++) {
            const uint32_t kb = (uint32_t)(kt * 32);
            uint32_t A0[4], A1[4];
            ldsm4(A0, aAddr0 + kb);
            ldsm4(A1, aAddr1 + kb);
            #pragma unroll
            for (int np = 0; np < 2; np++) {
                uint32_t B4[4];
                ldsm4(B4, bAddr + (uint32_t)(np * 16 * ASTR) + kb);
                mma_f16(d[0][np * 2 + 0], A0, B4 + 0);
                mma_f16(d[1][np * 2 + 0], A1, B4 + 0);
                mma_f16(d[0][np * 2 + 1], A0, B4 + 2);
                mma_f16(d[1][np * 2 + 1], A1, B4 + 2);
            }
        }

        // ---- store partials [row][b] ----
        {
            const int r0 = wm * 32 + (l >> 2);
            const int c0 = wn * 32 + (l & 3) * 2;
            #pragma unroll
            for (int mt = 0; mt < 2; mt++) {
                #pragma unroll
                for (int nt = 0; nt < 4; nt++) {
                    int row = r0 + mt * 16;
                    int col = c0 + nt * 8;
                    *(float2*)(ppart + (size_t)row * BATCH + col) =
                        make_float2(d[mt][nt][0], d[mt][nt][1]);
                    *(float2*)(ppart + (size_t)(row + 8) * BATCH + col) =
                        make_float2(d[mt][nt][2], d[mt][nt][3]);
                }
            }
        }

        // ---- bar1 arrive EARLY (partials done), then stage x(t+1), then wait ----
        __syncthreads();                       // partial stores CTA-wide complete
        if (tid == 0) {
            __threadfence();                   // release partial stores
            atomicAdd((unsigned*)grpc, 1u);
        }
        if (t + 1 < SEQ) {                     // x-stage overlaps others' arrivals
            const uint4* xs = (const uint4*)(g_xh + (size_t)(t + 1) * BATCH * INPUT + x_off);
            *(uint4*)(b_row + 512 + stf * 32)      = __ldcg(xs + 0);
            *(uint4*)(b_row + 512 + stf * 32 + 16) = __ldcg(xs + 1);
        }
        if (tid == 0) {                        // bare spin (no nanosleep)
            const unsigned tgt1 = (unsigned)(t + 1) * NKS;
            while (*grpc < tgt1) { }
            __threadfence();
        }
        __syncthreads();

        const size_t hw = (size_t)((t + 1) & 1) * BH;

        // ---- reduce 4 k-slices + pointwise (2 cells) -> smem exchange ----
        {
            float accA[4], accB[4];
            #pragma unroll
            for (int g = 0; g < 4; g++) { accA[g] = biasA[g]; accB[g] = biasB[g]; }
            #pragma unroll
            for (int g = 0; g < 4; g++) {
                #pragma unroll
                for (int s = 0; s < NKS; s++) {
                    const float* pp = g_part + (size_t)(s * NM + mg) * RPC * BATCH + pb;
                    accA[g] += __ldcg(pp + (size_t)(g * 32 + jlA) * BATCH);
                    accB[g] += __ldcg(pp + (size_t)(g * 32 + jlB) * BATCH);
                }
            }
            float f, i1, i2, o, hvA, hvB;

            f = sigm(accA[0]); i1 = sigm(accA[1]); i2 = tanhf(accA[2]); o = sigm(accA[3]);
            cA = cA * f + i1 * i2;
            hvA = tanhf(cA) * o;

            f = sigm(accB[0]); i1 = sigm(accB[1]); i2 = tanhf(accB[2]); o = sigm(accB[3]);
            cB = cB * f + i1 * i2;
            hvB = tanhf(cB) * o;

            harea[lb * 32 + jlA] = __float2half_rn(hvA);
            harea[lb * 32 + jlB] = __float2half_rn(hvB);
            oarea[lb * 32 + jlA] = hvA;
            oarea[lb * 32 + jlB] = hvB;

            if (t == SEQ - 1) {      // final h, c (once; scattered is fine)
                out[SBH + (size_t)pb * HID + jA] = hvA;
                out[SBH + BH + (size_t)pb * HID + jA] = cA;
                out[SBH + (size_t)pb * HID + jB] = hvB;
                out[SBH + BH + (size_t)pb * HID + jB] = cB;
            }
        }
        __syncthreads();                       // exchange areas visible

        // ---- coalesced h copy (only this gates the ready flag) ----
        if (tid < 64) {
            int b = tid >> 2, q = tid & 3;
            *(uint4*)(g_hh + hw + (size_t)(ks * 16 + b) * HID + j0 + q * 8) =
                *(uint4*)(harea + b * 32 + q * 8);
        }
        __syncthreads();                       // h copy CTA-wide complete

        // ---- ready arrive + dep-wait (bare spins) + out-copy off critical path ----
        if (t + 1 < SEQ) {
            if (tid == 0) {
                __threadfence();               // release h stores
                atomicAdd(readyc, 1u);
            }
            if (tid >= 1 && tid <= 9) {
                const unsigned tgt = (unsigned)(t + 1) * NKS;
                while (*depc < tgt) { }
                __threadfence();
            }
        }
        if (tid >= 128) {                      // out copy overlaps the spins
            int u = tid - 128;
            int b = u >> 3, q = u & 7;
            *(float4*)(out + (size_t)t * BH + (size_t)(ks * 16 + b) * HID + j0 + q * 4) =
                *(float4*)(oarea + b * 32 + q * 4);
        }
        __syncthreads();

        // ---- stage h(t+1) from buf[(t+1)&1] ----
        if (t + 1 < SEQ) {
            const uint4* hs = (const uint4*)(g_hh + hw + hoff);
            #pragma unroll
            for (int q = 0; q < 8; q++)
                *(uint4*)(b_row + stf * 128 + q * 16) = __ldcg(hs + q);
            __syncthreads();
        }
    }
}

// ---------------------------------------------------------------------------
extern "C" void kernel_launch(void* const* d_in, const int* in_sizes, int n_in,
                              void* d_out, int out_size) {
    Params P;
    P.x = (const float*)d_in[0];
    P.Wx[0] = (const float*)d_in[1];  P.bx[0] = (const float*)d_in[2];
    P.Wx[1] = (const float*)d_in[3];  P.bx[1] = (const float*)d_in[4];
    P.Wx[2] = (const float*)d_in[5];  P.bx[2] = (const float*)d_in[6];
    P.Wx[3] = (const float*)d_in[7];  P.bx[3] = (const float*)d_in[8];
    P.Wh[0] = (const float*)d_in[9];  P.bh[0] = (const float*)d_in[10];
    P.Wh[1] = (const float*)d_in[11]; P.bh[1] = (const float*)d_in[12];
    P.Wh[2] = (const float*)d_in[13]; P.bh[2] = (const float*)d_in[14];
    P.Wh[3] = (const float*)d_in[15]; P.bh[3] = (const float*)d_in[16];
    P.out   = (float*)d_out;

    static bool attr_set = false;
    if (!attr_set) {
        cudaFuncSetAttribute(lstm_mma, cudaFuncAttributeMaxDynamicSharedMemorySize,
                             SMEM_TOTAL);
        attr_set = true;
    }

    init_kernel<<<(SEQ * BATCH * INPUT / 4 + 255) / 256, 256>>>(P.x);
    lstm_mma<<<NCTA, NTHR, SMEM_TOTAL>>>(P);
}